// round 4
// baseline (speedup 1.0000x reference)
#include <cuda_runtime.h>
#include <cstdint>
#include <math.h>

#define BB 32
#define LL 64
#define EE 512
#define UU 512
#define VV 32000
#define J4 2048   // 4*UU
#define NBLK 128  // persistent LSTM blocks

// ---------------- device scratch ----------------
__device__ float g_wmask[BB*EE];
__device__ float g_rmask[4*BB*UU];
__device__ float g_fmask[BB*LL*UU];
__device__ float g_x[LL*BB*EE];
__device__ float g_zin[LL*BB*J4];
__device__ float g_hmT[2][4][UU][BB];   // double-buffered h*mask, transposed [g][u][b]
__device__ float g_rnn[BB*LL*UU];
__device__ unsigned g_bar;
__device__ int   g_is64;

// ---------------- threefry2x32 ----------------
__host__ __device__ inline void tf2x32(uint32_t k0, uint32_t k1,
                                       uint32_t x0, uint32_t x1,
                                       uint32_t* o0, uint32_t* o1)
{
    uint32_t ks2 = k0 ^ k1 ^ 0x1BD11BDAu;
    x0 += k0; x1 += k1;
#define RND(r) { x0 += x1; x1 = (x1 << (r)) | (x1 >> (32 - (r))); x1 ^= x0; }
    RND(13) RND(15) RND(26) RND(6)  x0 += k1;  x1 += ks2 + 1u;
    RND(17) RND(29) RND(16) RND(24) x0 += ks2; x1 += k0  + 2u;
    RND(13) RND(15) RND(26) RND(6)  x0 += k0;  x1 += k1  + 3u;
    RND(17) RND(29) RND(16) RND(24) x0 += k1;  x1 += ks2 + 4u;
    RND(13) RND(15) RND(26) RND(6)  x0 += ks2; x1 += k0  + 5u;
#undef RND
    *o0 = x0; *o1 = x1;
}

__device__ inline float bern_mask(uint32_t bits)
{
    float u = __uint_as_float((bits >> 9) | 0x3f800000u) - 1.0f;
    return (u < 0.7f) ? (1.0f / 0.7f) : 0.0f;
}

__global__ void mask_kernel(uint32_t k0, uint32_t k1, int n, float* out)
{
    int i = blockIdx.x * blockDim.x + threadIdx.x;
    if (i >= n) return;
    uint32_t o0, o1;
    tf2x32(k0, k1, 0u, (uint32_t)i, &o0, &o1);
    out[i] = bern_mask(o0 ^ o1);
}

__global__ void detect_kernel(const unsigned int* tw)
{
    __shared__ int flag;
    if (threadIdx.x == 0) flag = 1;
    __syncthreads();
    for (int i = threadIdx.x; i < 1024; i += 256)
        if (tw[2*i + 1] != 0u) atomicAnd(&flag, 0);
    __syncthreads();
    if (threadIdx.x == 0) { g_is64 = flag; g_bar = 0u; }
}

__global__ void embed_kernel(const float* __restrict__ images,
                             const void*  __restrict__ targs,
                             const float* __restrict__ emb)
{
    int idx = blockIdx.x * blockDim.x + threadIdx.x;
    int t = idx >> 14;
    int r = idx & 16383;
    int b = r >> 9;
    int e = r & 511;
    float val;
    if (t == 0) {
        val = images[b * EE + e];
    } else {
        int ti = b * LL + (t - 1);
        int tok = g_is64 ? (int)(((const long long*)targs)[ti])
                         : ((const int*)targs)[ti];
        val = emb[tok * EE + e] * g_wmask[b * EE + e];
    }
    g_x[idx] = val;
}

// ---------------- fp32 SGEMM for zin ----------------
__global__ __launch_bounds__(256) void sgemm128(const float* __restrict__ A,
                                                const float* __restrict__ Bm,
                                                const float* __restrict__ bias,
                                                float* __restrict__ C,
                                                int M, int N, int K)
{
    __shared__ float Ast[8][128];
    __shared__ float Bs[8][128];
    int tid = threadIdx.x;
    int bm0 = blockIdx.y * 128, bn0 = blockIdx.x * 128;
    int tx = tid & 15, ty = tid >> 4;

    float acc[8][8];
#pragma unroll
    for (int i = 0; i < 8; i++)
#pragma unroll
        for (int j = 0; j < 8; j++) acc[i][j] = 0.0f;

    int arow = tid >> 1, ak = (tid & 1) * 4;
    int bkr = tid >> 5, bc = (tid & 31) * 4;

    for (int k0 = 0; k0 < K; k0 += 8) {
        float4 av = *(const float4*)&A[(size_t)(bm0 + arow) * K + k0 + ak];
        Ast[ak + 0][arow] = av.x; Ast[ak + 1][arow] = av.y;
        Ast[ak + 2][arow] = av.z; Ast[ak + 3][arow] = av.w;
        float4 bv = *(const float4*)&Bm[(size_t)(k0 + bkr) * N + bn0 + bc];
        *(float4*)&Bs[bkr][bc] = bv;
        __syncthreads();
#pragma unroll
        for (int kk = 0; kk < 8; kk++) {
            float a[8], b[8];
#pragma unroll
            for (int i = 0; i < 8; i++) a[i] = Ast[kk][ty * 8 + i];
#pragma unroll
            for (int j = 0; j < 8; j++) b[j] = Bs[kk][tx * 8 + j];
#pragma unroll
            for (int i = 0; i < 8; i++)
#pragma unroll
                for (int j = 0; j < 8; j++) acc[i][j] += a[i] * b[j];
        }
        __syncthreads();
    }
#pragma unroll
    for (int i = 0; i < 8; i++) {
        int row = bm0 + ty * 8 + i;
#pragma unroll
        for (int j = 0; j < 8; j++) {
            int col = bn0 + tx * 8 + j;
            C[(size_t)row * N + col] = acc[i][j] + bias[col];
        }
    }
}

// ---------------- persistent LSTM ----------------
__device__ __forceinline__ void gridbar(unsigned target)
{
    __syncthreads();
    if (threadIdx.x == 0) {
        __threadfence();
        atomicAdd(&g_bar, 1u);
        unsigned v;
        do {
            asm volatile("ld.global.acquire.gpu.u32 %0, [%1];"
                         : "=r"(v) : "l"(&g_bar));
        } while (v < target);
    }
    __syncthreads();
}

__global__ __launch_bounds__(256, 1) void lstm_persist(const float* __restrict__ Wrec)
{
    __shared__ float sW[16][512];   // Wrec slice, [combo][k], resident all 64 steps
    __shared__ float sZ[16][32];    // z exchange [combo][b]

    int tid = threadIdx.x, bx = blockIdx.x;
    int u0 = bx * 4;                          // per-gate column offset
    int combo = tid >> 4;                     // 0..15 = g*4+j
    int g = combo >> 2, j = combo & 3;
    int bq = tid & 15, b0 = bq * 2;

    // stage Wrec slice (transposed for sequential-k reads)
    for (int idx = tid; idx < 16 * 512; idx += 256) {
        int cc = idx & 15, k = idx >> 4;
        int gg = cc >> 2, jj = cc & 3;
        sW[cc][k] = Wrec[(size_t)k * J4 + gg * 512 + u0 + jj];
    }
    // zero own hmT slices (both buffers)
    for (int idx = tid; idx < 2 * 4 * 4 * 32; idx += 256) {
        int b  = idx & 31;
        int uu = (idx >> 5) & 3;
        int gg = (idx >> 7) & 3;
        int bf = idx >> 9;
        g_hmT[bf][gg][u0 + uu][b] = 0.0f;
    }
    float c_reg = 0.0f;                       // cell state (tid<128 owns (ju,bb))
    int bb = tid & 31, ju = tid >> 5;         // phase-B mapping
    int col = g * 512 + u0 + j;

    gridbar(NBLK);

    for (int t = 0; t < LL; t++) {
        int rbuf = (t + 1) & 1, wbuf = t & 1;

        // ---- phase A: z = zin + hm @ Wrec (this block's 16 columns) ----
        float acc0 = g_zin[t * (BB*J4) + b0 * J4 + col];
        float acc1 = g_zin[t * (BB*J4) + (b0 + 1) * J4 + col];
        const float*  wrow = sW[combo];
        const float2* hp   = (const float2*)&g_hmT[rbuf][g][0][b0];  // stride 16 float2 per k
#pragma unroll 2
        for (int k = 0; k < 512; k += 4) {
            float4 w  = *(const float4*)&wrow[k];
            float2 h0 = __ldcg(hp + (k + 0) * 16);
            float2 h1 = __ldcg(hp + (k + 1) * 16);
            float2 h2 = __ldcg(hp + (k + 2) * 16);
            float2 h3 = __ldcg(hp + (k + 3) * 16);
            acc0 += w.x * h0.x; acc1 += w.x * h0.y;
            acc0 += w.y * h1.x; acc1 += w.y * h1.y;
            acc0 += w.z * h2.x; acc1 += w.z * h2.y;
            acc0 += w.w * h3.x; acc1 += w.w * h3.y;
        }
        sZ[combo][b0]     = acc0;
        sZ[combo][b0 + 1] = acc1;
        __syncthreads();

        // ---- phase B: gates for (u0+ju, bb), c in registers ----
        if (tid < 128) {
            float zi = sZ[0 * 4 + ju][bb];
            float zf = sZ[1 * 4 + ju][bb];
            float zg = sZ[2 * 4 + ju][bb];
            float zo = sZ[3 * 4 + ju][bb];
            float ig = 1.0f / (1.0f + expf(-zi));
            float fg = 1.0f / (1.0f + expf(-zf));
            float gg = tanhf(zg);
            float og = 1.0f / (1.0f + expf(-zo));
            c_reg = fg * c_reg + ig * gg;
            float h = og * tanhf(c_reg);
            int u = u0 + ju;
#pragma unroll
            for (int g2 = 0; g2 < 4; g2++)
                g_hmT[wbuf][g2][u][bb] = h * g_rmask[g2 * (BB*UU) + bb * UU + u];
            g_rnn[(bb * LL + t) * UU + u] = h * g_fmask[(bb * LL + t) * UU + u];
        }
        gridbar((unsigned)(t + 2) * NBLK);
    }
}

// ---------------- tf32 tensor-core GEMM (CVT-free inner loop) ----------------
__device__ inline uint32_t f2tf32(float x)
{
    uint32_t r;
    asm("cvt.rna.tf32.f32 %0, %1;" : "=r"(r) : "f"(x));
    return r;
}

// A slot for value k (0..15) at row r: pair-swizzled so (k,k+4) is one LDS.64
__device__ __forceinline__ int a_slot(int k, int r)
{
    int grp = k >> 3, kw = k & 7;
    return grp * 8 + 2 * ((kw & 3) ^ ((r >> 1) & 3)) + (kw >> 2);
}

__global__ __launch_bounds__(256) void tgemm_tf32(const float* __restrict__ A,
                                                  const float* __restrict__ Bm,
                                                  const float* __restrict__ bias,
                                                  float* __restrict__ C,
                                                  int M, int N, int K)
{
    __shared__ uint32_t As[2][128][16];   // tf32 bits, pair-swizzled
    __shared__ uint32_t Bs[2][16][132];   // tf32 bits, [k][col] padded

    int tid  = threadIdx.x;
    int lane = tid & 31, wid = tid >> 5;
    int wm0 = (wid >> 2) * 64;
    int wn0 = (wid & 3) * 32;
    int bm = blockIdx.y * 128, bn = blockIdx.x * 128;
    int t4 = lane >> 2, tq = lane & 3;

    int arow = tid >> 1, ac = (tid & 1) * 4;
    int brow = tid >> 4, bc = (tid & 15) * 8;

    const float* Abase = A + (size_t)(bm + arow) * K + ac;
    const float* Bbase = Bm + (size_t)brow * N + bn + bc;

    float4 av0, av1, bv0, bv1;

    float acc[4][4][4];
#pragma unroll
    for (int i = 0; i < 4; i++)
#pragma unroll
        for (int j = 0; j < 4; j++)
#pragma unroll
            for (int k = 0; k < 4; k++) acc[i][j][k] = 0.0f;

    // store helpers (convert once, outside MMA loop)
#define STORE_TILE(buf)                                                          \
    {                                                                            \
        As[buf][arow][a_slot(ac + 0, arow)]     = f2tf32(av0.x);                 \
        As[buf][arow][a_slot(ac + 1, arow)]     = f2tf32(av0.y);                 \
        As[buf][arow][a_slot(ac + 2, arow)]     = f2tf32(av0.z);                 \
        As[buf][arow][a_slot(ac + 3, arow)]     = f2tf32(av0.w);                 \
        As[buf][arow][a_slot(ac + 8, arow)]     = f2tf32(av1.x);                 \
        As[buf][arow][a_slot(ac + 9, arow)]     = f2tf32(av1.y);                 \
        As[buf][arow][a_slot(ac + 10, arow)]    = f2tf32(av1.z);                 \
        As[buf][arow][a_slot(ac + 11, arow)]    = f2tf32(av1.w);                 \
        uint4 cb0 = make_uint4(f2tf32(bv0.x), f2tf32(bv0.y),                     \
                               f2tf32(bv0.z), f2tf32(bv0.w));                    \
        uint4 cb1 = make_uint4(f2tf32(bv1.x), f2tf32(bv1.y),                     \
                               f2tf32(bv1.z), f2tf32(bv1.w));                    \
        *(uint4*)&Bs[buf][brow][bc]     = cb0;                                   \
        *(uint4*)&Bs[buf][brow][bc + 4] = cb1;                                   \
    }

    // prologue
    av0 = *(const float4*)(Abase);
    av1 = *(const float4*)(Abase + 8);
    bv0 = *(const float4*)(Bbase);
    bv1 = *(const float4*)(Bbase + 4);
    STORE_TILE(0);
    __syncthreads();

    int nt = K / 16;
    for (int kt = 0; kt < nt; kt++) {
        int cur = kt & 1;
        if (kt + 1 < nt) {
            const float* ap = Abase + (kt + 1) * 16;
            const float* bp = Bbase + (size_t)(kt + 1) * 16 * N;
            av0 = *(const float4*)(ap);
            av1 = *(const float4*)(ap + 8);
            bv0 = *(const float4*)(bp);
            bv1 = *(const float4*)(bp + 4);
        }
#pragma unroll
        for (int kk = 0; kk < 16; kk += 8) {
            uint32_t af[4][4], bf[4][2];
#pragma unroll
            for (int mi = 0; mi < 4; mi++) {
                int r0 = wm0 + mi * 16 + t4;
                int r1 = r0 + 8;
                uint2 p0 = *(const uint2*)&As[cur][r0][kk + 2 * (tq ^ ((r0 >> 1) & 3))];
                uint2 p1 = *(const uint2*)&As[cur][r1][kk + 2 * (tq ^ ((r1 >> 1) & 3))];
                af[mi][0] = p0.x; af[mi][2] = p0.y;
                af[mi][1] = p1.x; af[mi][3] = p1.y;
            }
#pragma unroll
            for (int nj = 0; nj < 4; nj++) {
                int ccol = wn0 + nj * 8 + t4;
                bf[nj][0] = Bs[cur][kk + tq][ccol];
                bf[nj][1] = Bs[cur][kk + 4 + tq][ccol];
            }
#pragma unroll
            for (int mi = 0; mi < 4; mi++)
#pragma unroll
                for (int nj = 0; nj < 4; nj++) {
                    asm volatile(
                        "mma.sync.aligned.m16n8k8.row.col.f32.tf32.tf32.f32 "
                        "{%0,%1,%2,%3}, {%4,%5,%6,%7}, {%8,%9}, {%0,%1,%2,%3};"
                        : "+f"(acc[mi][nj][0]), "+f"(acc[mi][nj][1]),
                          "+f"(acc[mi][nj][2]), "+f"(acc[mi][nj][3])
                        : "r"(af[mi][0]), "r"(af[mi][1]), "r"(af[mi][2]), "r"(af[mi][3]),
                          "r"(bf[nj][0]), "r"(bf[nj][1]));
                }
        }
        if (kt + 1 < nt) {
            __syncthreads();
            int nxt = (kt + 1) & 1;
            STORE_TILE(nxt);
            __syncthreads();
        }
    }
#undef STORE_TILE

    // epilogue
#pragma unroll
    for (int mi = 0; mi < 4; mi++) {
        int r0 = bm + wm0 + mi * 16 + t4;
#pragma unroll
        for (int nj = 0; nj < 4; nj++) {
            int col = bn + wn0 + nj * 8 + tq * 2;
            float b0 = bias[col], b1 = bias[col + 1];
            float2 v0 = make_float2(acc[mi][nj][0] + b0, acc[mi][nj][1] + b1);
            float2 v1 = make_float2(acc[mi][nj][2] + b0, acc[mi][nj][3] + b1);
            *(float2*)&C[(size_t)r0 * N + col]       = v0;
            *(float2*)&C[(size_t)(r0 + 8) * N + col] = v1;
        }
    }
}

// ---------------- launch ----------------
extern "C" void kernel_launch(void* const* d_in, const int* in_sizes, int n_in,
                              void* d_out, int out_size)
{
    const float* images = (const float*)d_in[1];
    const void*  targs  =                d_in[2];
    const float* emb    = (const float*)d_in[3];
    const float* W_in   = (const float*)d_in[4];
    const float* W_rec  = (const float*)d_in[5];
    const float* b_lstm = (const float*)d_in[6];
    const float* W_out  = (const float*)d_in[7];
    const float* b_out  = (const float*)d_in[8];
    float* out = (float*)d_out;

    uint32_t k1a,k1b, k2a,k2b, k3a,k3b;
    tf2x32(0u, 42u, 0u, 0u, &k1a, &k1b);
    tf2x32(0u, 42u, 0u, 1u, &k2a, &k2b);
    tf2x32(0u, 42u, 0u, 2u, &k3a, &k3b);

    float *p_wmask, *p_rmask, *p_fmask, *p_x, *p_zin, *p_rnn;
    cudaGetSymbolAddress((void**)&p_wmask, g_wmask);
    cudaGetSymbolAddress((void**)&p_rmask, g_rmask);
    cudaGetSymbolAddress((void**)&p_fmask, g_fmask);
    cudaGetSymbolAddress((void**)&p_x,     g_x);
    cudaGetSymbolAddress((void**)&p_zin,   g_zin);
    cudaGetSymbolAddress((void**)&p_rnn,   g_rnn);

    detect_kernel<<<1, 256>>>((const unsigned int*)targs);   // also resets g_bar

    mask_kernel<<<(BB*EE)    / 256, 256>>>(k1a, k1b, BB*EE,    p_wmask);
    mask_kernel<<<(4*BB*UU)  / 256, 256>>>(k2a, k2b, 4*BB*UU,  p_rmask);
    mask_kernel<<<(BB*LL*UU) / 256, 256>>>(k3a, k3b, BB*LL*UU, p_fmask);

    embed_kernel<<<(LL*BB*EE) / 256, 256>>>(images, targs, emb);

    sgemm128<<<dim3(J4/128, (LL*BB)/128), 256>>>(p_x, W_in, b_lstm, p_zin, LL*BB, J4, EE);

    lstm_persist<<<NBLK, 256>>>(W_rec);

    tgemm_tf32<<<dim3(VV/128, (BB*LL)/128), 256>>>(p_rnn, W_out, b_out, out, BB*LL, VV, UU);
}

// round 5
// speedup vs baseline: 1.4165x; 1.4165x over previous
#include <cuda_runtime.h>
#include <cstdint>
#include <math.h>

#define BB 32
#define LL 64
#define EE 512
#define UU 512
#define VV 32000
#define J4 2048   // 4*UU
#define NBLK 128  // persistent LSTM blocks

// ---------------- device scratch ----------------
__device__ float g_wmask[BB*EE];
__device__ float g_rmask[4*BB*UU];
__device__ float g_fmask[BB*LL*UU];
__device__ float g_x[LL*BB*EE];
__device__ float g_zin[LL*BB*J4];
__device__ float g_hmB[2][4][UU][BB];   // [buf][gate][u(k)][batch] — b contiguous
__device__ float g_rnn[BB*LL*UU];
__device__ unsigned g_bar;
__device__ int   g_is64;

// ---------------- threefry2x32 (JAX partitionable) ----------------
__host__ __device__ inline void tf2x32(uint32_t k0, uint32_t k1,
                                       uint32_t x0, uint32_t x1,
                                       uint32_t* o0, uint32_t* o1)
{
    uint32_t ks2 = k0 ^ k1 ^ 0x1BD11BDAu;
    x0 += k0; x1 += k1;
#define RND(r) { x0 += x1; x1 = (x1 << (r)) | (x1 >> (32 - (r))); x1 ^= x0; }
    RND(13) RND(15) RND(26) RND(6)  x0 += k1;  x1 += ks2 + 1u;
    RND(17) RND(29) RND(16) RND(24) x0 += ks2; x1 += k0  + 2u;
    RND(13) RND(15) RND(26) RND(6)  x0 += k0;  x1 += k1  + 3u;
    RND(17) RND(29) RND(16) RND(24) x0 += k1;  x1 += ks2 + 4u;
    RND(13) RND(15) RND(26) RND(6)  x0 += ks2; x1 += k0  + 5u;
#undef RND
    *o0 = x0; *o1 = x1;
}

__device__ inline float bern_mask(uint32_t bits)
{
    float u = __uint_as_float((bits >> 9) | 0x3f800000u) - 1.0f;
    return (u < 0.7f) ? (1.0f / 0.7f) : 0.0f;
}

// ---------------- prep: all masks + dtype detect + barrier reset ----------------
#define N_WM (BB*EE)          // 16384
#define N_RM (4*BB*UU)        // 65536
#define N_FM (BB*LL*UU)       // 1048576
#define PREP_BLOCKS ((N_WM + N_RM + N_FM) / 256 + 1)   // 4417

__global__ void prep_kernel(uint32_t wk0, uint32_t wk1,
                            uint32_t rk0, uint32_t rk1,
                            uint32_t fk0, uint32_t fk1,
                            const unsigned int* tw)
{
    int bx = blockIdx.x, tid = threadIdx.x;
    if (bx == PREP_BLOCKS - 1) {
        __shared__ int flag;
        if (tid == 0) flag = 1;
        __syncthreads();
        for (int i = tid; i < 1024; i += 256)
            if (tw[2*i + 1] != 0u) atomicAnd(&flag, 0);
        __syncthreads();
        if (tid == 0) { g_is64 = flag; g_bar = 0u; }
        return;
    }
    int i = bx * 256 + tid;
    uint32_t o0, o1;
    if (i < N_WM) {
        tf2x32(wk0, wk1, 0u, (uint32_t)i, &o0, &o1);
        g_wmask[i] = bern_mask(o0 ^ o1);
    } else if (i < N_WM + N_RM) {
        int j = i - N_WM;
        tf2x32(rk0, rk1, 0u, (uint32_t)j, &o0, &o1);
        g_rmask[j] = bern_mask(o0 ^ o1);
    } else {
        int j = i - N_WM - N_RM;
        tf2x32(fk0, fk1, 0u, (uint32_t)j, &o0, &o1);
        g_fmask[j] = bern_mask(o0 ^ o1);
    }
}

// ---------------- build X ----------------
__global__ void embed_kernel(const float* __restrict__ images,
                             const void*  __restrict__ targs,
                             const float* __restrict__ emb)
{
    int idx = blockIdx.x * blockDim.x + threadIdx.x;
    int t = idx >> 14;
    int r = idx & 16383;
    int b = r >> 9;
    int e = r & 511;
    float val;
    if (t == 0) {
        val = images[b * EE + e];
    } else {
        int ti = b * LL + (t - 1);
        int tok = g_is64 ? (int)(((const long long*)targs)[ti])
                         : ((const int*)targs)[ti];
        val = emb[tok * EE + e] * g_wmask[b * EE + e];
    }
    g_x[idx] = val;
}

// ---------------- fp32 SGEMM for zin (full precision feeds recurrence) ----------------
__global__ __launch_bounds__(256) void sgemm128(const float* __restrict__ A,
                                                const float* __restrict__ Bm,
                                                const float* __restrict__ bias,
                                                float* __restrict__ C,
                                                int M, int N, int K)
{
    __shared__ float Ast[8][128];
    __shared__ float Bs[8][128];
    int tid = threadIdx.x;
    int bm0 = blockIdx.y * 128, bn0 = blockIdx.x * 128;
    int tx = tid & 15, ty = tid >> 4;

    float acc[8][8];
#pragma unroll
    for (int i = 0; i < 8; i++)
#pragma unroll
        for (int j = 0; j < 8; j++) acc[i][j] = 0.0f;

    int arow = tid >> 1, ak = (tid & 1) * 4;
    int bkr = tid >> 5, bc = (tid & 31) * 4;

    for (int k0 = 0; k0 < K; k0 += 8) {
        float4 av = *(const float4*)&A[(size_t)(bm0 + arow) * K + k0 + ak];
        Ast[ak + 0][arow] = av.x; Ast[ak + 1][arow] = av.y;
        Ast[ak + 2][arow] = av.z; Ast[ak + 3][arow] = av.w;
        float4 bv = *(const float4*)&Bm[(size_t)(k0 + bkr) * N + bn0 + bc];
        *(float4*)&Bs[bkr][bc] = bv;
        __syncthreads();
#pragma unroll
        for (int kk = 0; kk < 8; kk++) {
            float a[8], b[8];
#pragma unroll
            for (int i = 0; i < 8; i++) a[i] = Ast[kk][ty * 8 + i];
#pragma unroll
            for (int j = 0; j < 8; j++) b[j] = Bs[kk][tx * 8 + j];
#pragma unroll
            for (int i = 0; i < 8; i++)
#pragma unroll
                for (int j = 0; j < 8; j++) acc[i][j] += a[i] * b[j];
        }
        __syncthreads();
    }
#pragma unroll
    for (int i = 0; i < 8; i++) {
        int row = bm0 + ty * 8 + i;
#pragma unroll
        for (int j = 0; j < 8; j++) {
            int col = bn0 + tx * 8 + j;
            C[(size_t)row * N + col] = acc[i][j] + bias[col];
        }
    }
}

// ---------------- persistent LSTM ----------------
__device__ __forceinline__ void gridbar(unsigned target)
{
    __syncthreads();
    if (threadIdx.x == 0) {
        __threadfence();
        atomicAdd(&g_bar, 1u);
        unsigned v;
        do {
            asm volatile("ld.global.acquire.gpu.u32 %0, [%1];"
                         : "=r"(v) : "l"(&g_bar));
        } while (v < target);
    }
    __syncthreads();
}

__global__ __launch_bounds__(256, 1) void lstm_persist(const float* __restrict__ Wrec)
{
    __shared__ float sW[16][520];    // pad 512->520: conflict-free 4-addr broadcast
    __shared__ float sZ[2][16][32];  // k-half partial sums

    int tid = threadIdx.x, bx = blockIdx.x;
    int u0 = bx * 4;

    // stage Wrec slice: combo c=(g,j) row holds W[:, g*512+u0+j]
    for (int idx = tid; idx < 16 * 512; idx += 256) {
        int c = idx & 15, k = idx >> 4;
        sW[c][k] = Wrec[(size_t)k * J4 + (c >> 2) * 512 + u0 + (c & 3)];
    }
    // zero hm buffers (each block 1/128 of 131072 floats)
    for (int idx = tid; idx < 1024; idx += 256)
        ((float*)g_hmB)[bx * 1024 + idx] = 0.0f;

    // phase-A mapping: warp = (g, k-half); lanes = j(4) x bq(8)
    int g  = tid >> 6;
    int kh = (tid >> 5) & 1;
    int j  = (tid >> 3) & 3;
    int bq = tid & 7;
    int b0 = bq * 4;
    int combo = g * 4 + j;
    int col = g * 512 + u0 + j;
    int kbase = kh * 256;

    // phase-B mapping (tid<128): lanes consecutive in u for coalesced stores
    int ju = tid & 3, bb = tid >> 2;
    int ub = u0 + ju;
    float c_reg = 0.0f;
    float rm[4];
    if (tid < 128) {
#pragma unroll
        for (int g2 = 0; g2 < 4; g2++)
            rm[g2] = g_rmask[g2 * (BB*UU) + bb * UU + ub];
    }

    gridbar(NBLK);

    for (int t = 0; t < LL; t++) {
        int rbuf = (t + 1) & 1, wbuf = t & 1;

        // ---- phase A: partial z over this thread's k-half, 4 batches ----
        float a0, a1, a2, a3;
        if (kh == 0) {
            const float* zp = &g_zin[t * (BB*J4) + b0 * J4 + col];
            a0 = zp[0]; a1 = zp[J4]; a2 = zp[2*J4]; a3 = zp[3*J4];
        } else {
            a0 = a1 = a2 = a3 = 0.0f;
        }
        const float4* hp = ((const float4*)g_hmB)
                         + ((size_t)(rbuf * 4 + g) * 512 + kbase) * 8 + bq;
        const float* wrow = &sW[combo][kbase];
#pragma unroll 4
        for (int k = 0; k < 256; k += 4) {
            float4 w  = *(const float4*)&wrow[k];
            float4 h0 = __ldcg(hp + (k + 0) * 8);
            float4 h1 = __ldcg(hp + (k + 1) * 8);
            float4 h2 = __ldcg(hp + (k + 2) * 8);
            float4 h3 = __ldcg(hp + (k + 3) * 8);
            a0 += w.x*h0.x + w.y*h1.x + w.z*h2.x + w.w*h3.x;
            a1 += w.x*h0.y + w.y*h1.y + w.z*h2.y + w.w*h3.y;
            a2 += w.x*h0.z + w.y*h1.z + w.z*h2.z + w.w*h3.z;
            a3 += w.x*h0.w + w.y*h1.w + w.z*h2.w + w.w*h3.w;
        }
        *(float4*)&sZ[kh][combo][b0] = make_float4(a0, a1, a2, a3);
        __syncthreads();

        // ---- phase B: gates for (ub, bb) ----
        if (tid < 128) {
            float zi = sZ[0][ju     ][bb] + sZ[1][ju     ][bb];
            float zf = sZ[0][4 + ju ][bb] + sZ[1][4 + ju ][bb];
            float zg = sZ[0][8 + ju ][bb] + sZ[1][8 + ju ][bb];
            float zo = sZ[0][12 + ju][bb] + sZ[1][12 + ju][bb];
            float ig = 1.0f / (1.0f + expf(-zi));
            float fg = 1.0f / (1.0f + expf(-zf));
            float gg = tanhf(zg);
            float og = 1.0f / (1.0f + expf(-zo));
            c_reg = fg * c_reg + ig * gg;
            float h = og * tanhf(c_reg);
#pragma unroll
            for (int g2 = 0; g2 < 4; g2++)
                g_hmB[wbuf][g2][ub][bb] = h * rm[g2];
            int row = bb * LL + t;
            g_rnn[row * UU + ub] = h * g_fmask[row * UU + ub];
        }
        gridbar((unsigned)(t + 2) * NBLK);
    }
}

// ---------------- tf32 tensor-core GEMM, fragment-pipelined ----------------
__device__ inline uint32_t f2tf32(float x)
{
    uint32_t r;
    asm("cvt.rna.tf32.f32 %0, %1;" : "=r"(r) : "f"(x));
    return r;
}

__global__ __launch_bounds__(256) void tgemm_tf32(const float* __restrict__ A,
                                                  const float* __restrict__ Bm,
                                                  const float* __restrict__ bias,
                                                  float* __restrict__ C,
                                                  int M, int N, int K)
{
    __shared__ uint32_t As[2][128][20];   // tf32 bits, padded (R3 layout)
    __shared__ uint32_t Bs[2][16][132];   // tf32 bits, padded

    int tid  = threadIdx.x;
    int lane = tid & 31, wid = tid >> 5;
    int wm0 = (wid >> 2) * 64;
    int wn0 = (wid & 3) * 32;
    int bm = blockIdx.y * 128, bn = blockIdx.x * 128;
    int t4 = lane >> 2, tq = lane & 3;

    int arow = tid >> 1, ac = (tid & 1) * 4;
    int brow = tid >> 4, bc = (tid & 15) * 8;

    const float* Abase = A + (size_t)(bm + arow) * K + ac;
    const float* Bbase = Bm + (size_t)brow * N + bn + bc;

    float4 av0, av1, bv0, bv1;

    float acc[4][4][4];
#pragma unroll
    for (int i = 0; i < 4; i++)
#pragma unroll
        for (int j = 0; j < 4; j++)
#pragma unroll
            for (int k = 0; k < 4; k++) acc[i][j][k] = 0.0f;

#define STORE_TILE(buf)                                                         \
    {                                                                           \
        uint4 ca0 = make_uint4(f2tf32(av0.x), f2tf32(av0.y),                    \
                               f2tf32(av0.z), f2tf32(av0.w));                   \
        uint4 ca1 = make_uint4(f2tf32(av1.x), f2tf32(av1.y),                    \
                               f2tf32(av1.z), f2tf32(av1.w));                   \
        *(uint4*)&As[buf][arow][ac]     = ca0;                                  \
        *(uint4*)&As[buf][arow][ac + 8] = ca1;                                  \
        uint4 cb0 = make_uint4(f2tf32(bv0.x), f2tf32(bv0.y),                    \
                               f2tf32(bv0.z), f2tf32(bv0.w));                   \
        uint4 cb1 = make_uint4(f2tf32(bv1.x), f2tf32(bv1.y),                    \
                               f2tf32(bv1.z), f2tf32(bv1.w));                   \
        *(uint4*)&Bs[buf][brow][bc]     = cb0;                                  \
        *(uint4*)&Bs[buf][brow][bc + 4] = cb1;                                  \
    }

#define LOADFRAG(af, bf, buf, kk)                                               \
    {                                                                           \
        _Pragma("unroll")                                                       \
        for (int mi = 0; mi < 4; mi++) {                                        \
            int r0 = wm0 + mi * 16 + t4;                                        \
            af[mi][0] = As[buf][r0    ][(kk) + tq];                             \
            af[mi][1] = As[buf][r0 + 8][(kk) + tq];                             \
            af[mi][2] = As[buf][r0    ][(kk) + 4 + tq];                         \
            af[mi][3] = As[buf][r0 + 8][(kk) + 4 + tq];                         \
        }                                                                       \
        _Pragma("unroll")                                                       \
        for (int nj = 0; nj < 4; nj++) {                                        \
            int ccol = wn0 + nj * 8 + t4;                                       \
            bf[nj][0] = Bs[buf][(kk) + tq][ccol];                               \
            bf[nj][1] = Bs[buf][(kk) + 4 + tq][ccol];                           \
        }                                                                       \
    }

#define MMA_SET(af, bf)                                                         \
    {                                                                           \
        _Pragma("unroll")                                                       \
        for (int mi = 0; mi < 4; mi++)                                          \
            _Pragma("unroll")                                                   \
            for (int nj = 0; nj < 4; nj++) {                                    \
                asm volatile(                                                   \
                    "mma.sync.aligned.m16n8k8.row.col.f32.tf32.tf32.f32 "       \
                    "{%0,%1,%2,%3}, {%4,%5,%6,%7}, {%8,%9}, {%0,%1,%2,%3};"     \
                    : "+f"(acc[mi][nj][0]), "+f"(acc[mi][nj][1]),               \
                      "+f"(acc[mi][nj][2]), "+f"(acc[mi][nj][3])                \
                    : "r"(af[mi][0]), "r"(af[mi][1]),                           \
                      "r"(af[mi][2]), "r"(af[mi][3]),                           \
                      "r"(bf[nj][0]), "r"(bf[nj][1]));                          \
            }                                                                   \
    }

    // prologue
    av0 = *(const float4*)(Abase);
    av1 = *(const float4*)(Abase + 8);
    bv0 = *(const float4*)(Bbase);
    bv1 = *(const float4*)(Bbase + 4);
    STORE_TILE(0);
    __syncthreads();

    uint32_t af0[4][4], bf0[4][2], af1[4][4], bf1[4][2];
    LOADFRAG(af0, bf0, 0, 0);

    int nt = K / 16;
    for (int kt = 0; kt < nt; kt++) {
        int cur = kt & 1;
        if (kt + 1 < nt) {
            const float* ap = Abase + (kt + 1) * 16;
            const float* bp = Bbase + (size_t)(kt + 1) * 16 * N;
            av0 = *(const float4*)(ap);
            av1 = *(const float4*)(ap + 8);
            bv0 = *(const float4*)(bp);
            bv1 = *(const float4*)(bp + 4);
        }
        LOADFRAG(af1, bf1, cur, 8);
        MMA_SET(af0, bf0);
        if (kt + 1 < nt) {
            int nxt = (kt + 1) & 1;
            __syncthreads();
            STORE_TILE(nxt);
            __syncthreads();
            LOADFRAG(af0, bf0, nxt, 0);
        }
        MMA_SET(af1, bf1);
    }
#undef STORE_TILE
#undef LOADFRAG
#undef MMA_SET

    // epilogue
#pragma unroll
    for (int mi = 0; mi < 4; mi++) {
        int r0 = bm + wm0 + mi * 16 + t4;
#pragma unroll
        for (int nj = 0; nj < 4; nj++) {
            int col = bn + wn0 + nj * 8 + tq * 2;
            float b0 = bias[col], b1 = bias[col + 1];
            float2 v0 = make_float2(acc[mi][nj][0] + b0, acc[mi][nj][1] + b1);
            float2 v1 = make_float2(acc[mi][nj][2] + b0, acc[mi][nj][3] + b1);
            *(float2*)&C[(size_t)r0 * N + col]       = v0;
            *(float2*)&C[(size_t)(r0 + 8) * N + col] = v1;
        }
    }
}

// ---------------- launch ----------------
extern "C" void kernel_launch(void* const* d_in, const int* in_sizes, int n_in,
                              void* d_out, int out_size)
{
    const float* images = (const float*)d_in[1];
    const void*  targs  =                d_in[2];
    const float* emb    = (const float*)d_in[3];
    const float* W_in   = (const float*)d_in[4];
    const float* W_rec  = (const float*)d_in[5];
    const float* b_lstm = (const float*)d_in[6];
    const float* W_out  = (const float*)d_in[7];
    const float* b_out  = (const float*)d_in[8];
    float* out = (float*)d_out;

    uint32_t k1a,k1b, k2a,k2b, k3a,k3b;
    tf2x32(0u, 42u, 0u, 0u, &k1a, &k1b);
    tf2x32(0u, 42u, 0u, 1u, &k2a, &k2b);
    tf2x32(0u, 42u, 0u, 2u, &k3a, &k3b);

    float *p_x, *p_zin, *p_rnn;
    cudaGetSymbolAddress((void**)&p_x,   g_x);
    cudaGetSymbolAddress((void**)&p_zin, g_zin);
    cudaGetSymbolAddress((void**)&p_rnn, g_rnn);

    // launch 0: prep (masks + detect + barrier reset)
    prep_kernel<<<PREP_BLOCKS, 256>>>(k1a, k1b, k2a, k2b, k3a, k3b,
                                      (const unsigned int*)targs);
    // launch 1: embed
    embed_kernel<<<(LL*BB*EE) / 256, 256>>>(images, targs, emb);
    // launch 2: zin GEMM (fp32)
    sgemm128<<<dim3(J4/128, (LL*BB)/128), 256>>>(p_x, W_in, b_lstm, p_zin, LL*BB, J4, EE);
    // launch 3 (ncu-captured): persistent LSTM
    lstm_persist<<<NBLK, 256>>>(W_rec);
    // launch 4: output projection (tf32 tensor cores)
    tgemm_tf32<<<dim3(VV/128, (BB*LL)/128), 256>>>(p_rnn, W_out, b_out, out, BB*LL, VV, UU);
}

// round 6
// speedup vs baseline: 1.4805x; 1.0452x over previous
#include <cuda_runtime.h>
#include <cstdint>
#include <math.h>

#define BB 32
#define LL 64
#define EE 512
#define UU 512
#define VV 32000
#define J4 2048   // 4*UU
#define NBLK 128  // persistent LSTM blocks

// ---------------- device scratch ----------------
__device__ float g_wmask[BB*EE];
__device__ float g_rmask[4*BB*UU];
__device__ float g_fmask[BB*LL*UU];
__device__ float g_x[LL*BB*EE];
__device__ float g_zin[LL*BB*J4];
__device__ float g_hmB[2][4][UU][BB];   // [buf][gate][u(k)][batch] — b contiguous
__device__ float g_rnn[BB*LL*UU];
__device__ unsigned g_bar;
__device__ int   g_is64;

// ---------------- threefry2x32 (JAX partitionable) ----------------
__host__ __device__ inline void tf2x32(uint32_t k0, uint32_t k1,
                                       uint32_t x0, uint32_t x1,
                                       uint32_t* o0, uint32_t* o1)
{
    uint32_t ks2 = k0 ^ k1 ^ 0x1BD11BDAu;
    x0 += k0; x1 += k1;
#define RND(r) { x0 += x1; x1 = (x1 << (r)) | (x1 >> (32 - (r))); x1 ^= x0; }
    RND(13) RND(15) RND(26) RND(6)  x0 += k1;  x1 += ks2 + 1u;
    RND(17) RND(29) RND(16) RND(24) x0 += ks2; x1 += k0  + 2u;
    RND(13) RND(15) RND(26) RND(6)  x0 += k0;  x1 += k1  + 3u;
    RND(17) RND(29) RND(16) RND(24) x0 += k1;  x1 += ks2 + 4u;
    RND(13) RND(15) RND(26) RND(6)  x0 += ks2; x1 += k0  + 5u;
#undef RND
    *o0 = x0; *o1 = x1;
}

__device__ inline float bern_mask(uint32_t bits)
{
    float u = __uint_as_float((bits >> 9) | 0x3f800000u) - 1.0f;
    return (u < 0.7f) ? (1.0f / 0.7f) : 0.0f;
}

// ---------------- prep: all masks + dtype detect + barrier reset ----------------
#define N_WM (BB*EE)          // 16384
#define N_RM (4*BB*UU)        // 65536
#define N_FM (BB*LL*UU)       // 1048576
#define PREP_BLOCKS ((N_WM + N_RM + N_FM) / 256 + 1)   // 4417

__global__ void prep_kernel(uint32_t wk0, uint32_t wk1,
                            uint32_t rk0, uint32_t rk1,
                            uint32_t fk0, uint32_t fk1,
                            const unsigned int* tw)
{
    int bx = blockIdx.x, tid = threadIdx.x;
    if (bx == PREP_BLOCKS - 1) {
        __shared__ int flag;
        if (tid == 0) flag = 1;
        __syncthreads();
        for (int i = tid; i < 1024; i += 256)
            if (tw[2*i + 1] != 0u) atomicAnd(&flag, 0);
        __syncthreads();
        if (tid == 0) { g_is64 = flag; g_bar = 0u; }
        return;
    }
    int i = bx * 256 + tid;
    uint32_t o0, o1;
    if (i < N_WM) {
        tf2x32(wk0, wk1, 0u, (uint32_t)i, &o0, &o1);
        g_wmask[i] = bern_mask(o0 ^ o1);
    } else if (i < N_WM + N_RM) {
        int j = i - N_WM;
        tf2x32(rk0, rk1, 0u, (uint32_t)j, &o0, &o1);
        g_rmask[j] = bern_mask(o0 ^ o1);
    } else {
        int j = i - N_WM - N_RM;
        tf2x32(fk0, fk1, 0u, (uint32_t)j, &o0, &o1);
        g_fmask[j] = bern_mask(o0 ^ o1);
    }
}

// ---------------- build X ----------------
__global__ void embed_kernel(const float* __restrict__ images,
                             const void*  __restrict__ targs,
                             const float* __restrict__ emb)
{
    int idx = blockIdx.x * blockDim.x + threadIdx.x;
    int t = idx >> 14;
    int r = idx & 16383;
    int b = r >> 9;
    int e = r & 511;
    float val;
    if (t == 0) {
        val = images[b * EE + e];
    } else {
        int ti = b * LL + (t - 1);
        int tok = g_is64 ? (int)(((const long long*)targs)[ti])
                         : ((const int*)targs)[ti];
        val = emb[tok * EE + e] * g_wmask[b * EE + e];
    }
    g_x[idx] = val;
}

// ---------------- fp32 SGEMM for zin (full precision feeds recurrence) ----------------
__global__ __launch_bounds__(256) void sgemm128(const float* __restrict__ A,
                                                const float* __restrict__ Bm,
                                                const float* __restrict__ bias,
                                                float* __restrict__ C,
                                                int M, int N, int K)
{
    __shared__ float Ast[8][128];
    __shared__ float Bs[8][128];
    int tid = threadIdx.x;
    int bm0 = blockIdx.y * 128, bn0 = blockIdx.x * 128;
    int tx = tid & 15, ty = tid >> 4;

    float acc[8][8];
#pragma unroll
    for (int i = 0; i < 8; i++)
#pragma unroll
        for (int j = 0; j < 8; j++) acc[i][j] = 0.0f;

    int arow = tid >> 1, ak = (tid & 1) * 4;
    int bkr = tid >> 5, bc = (tid & 31) * 4;

    for (int k0 = 0; k0 < K; k0 += 8) {
        float4 av = *(const float4*)&A[(size_t)(bm0 + arow) * K + k0 + ak];
        Ast[ak + 0][arow] = av.x; Ast[ak + 1][arow] = av.y;
        Ast[ak + 2][arow] = av.z; Ast[ak + 3][arow] = av.w;
        float4 bv = *(const float4*)&Bm[(size_t)(k0 + bkr) * N + bn0 + bc];
        *(float4*)&Bs[bkr][bc] = bv;
        __syncthreads();
#pragma unroll
        for (int kk = 0; kk < 8; kk++) {
            float a[8], b[8];
#pragma unroll
            for (int i = 0; i < 8; i++) a[i] = Ast[kk][ty * 8 + i];
#pragma unroll
            for (int j = 0; j < 8; j++) b[j] = Bs[kk][tx * 8 + j];
#pragma unroll
            for (int i = 0; i < 8; i++)
#pragma unroll
                for (int j = 0; j < 8; j++) acc[i][j] += a[i] * b[j];
        }
        __syncthreads();
    }
#pragma unroll
    for (int i = 0; i < 8; i++) {
        int row = bm0 + ty * 8 + i;
#pragma unroll
        for (int j = 0; j < 8; j++) {
            int col = bn0 + tx * 8 + j;
            C[(size_t)row * N + col] = acc[i][j] + bias[col];
        }
    }
}

// ---------------- persistent LSTM (512 threads, k-split 4) ----------------
__device__ __forceinline__ void gridbar(unsigned target)
{
    __syncthreads();
    if (threadIdx.x == 0) {
        __threadfence();
        atomicAdd(&g_bar, 1u);
        unsigned v;
        do {
            asm volatile("ld.global.acquire.gpu.u32 %0, [%1];"
                         : "=r"(v) : "l"(&g_bar));
        } while (v < target);
    }
    __syncthreads();
}

__global__ __launch_bounds__(512, 1) void lstm_persist(const float* __restrict__ Wrec)
{
    __shared__ float sW[16][520];    // pad: conflict-free float4 broadcast
    __shared__ float sZ[4][16][32];  // k-quarter partial sums

    int tid = threadIdx.x, bx = blockIdx.x;
    int u0 = bx * 4;

    // stage Wrec slice: combo c=(g,j) row holds W[:, g*512+u0+j]
    for (int idx = tid; idx < 16 * 512; idx += 512) {
        int c = idx & 15, k = idx >> 4;
        sW[c][k] = Wrec[(size_t)k * J4 + (c >> 2) * 512 + u0 + (c & 3)];
    }
    // zero hm buffers (block's 1/128 share of 131072 floats)
    for (int idx = tid; idx < 1024; idx += 512)
        ((float*)g_hmB)[bx * 1024 + idx] = 0.0f;

    // phase-A mapping: warp = (g, kq); lanes = j(4) x bq(8)
    int g  = tid >> 7;
    int kq = (tid >> 5) & 3;
    int j  = (tid >> 3) & 3;
    int bq = tid & 7;
    int b0 = bq * 4;
    int combo = g * 4 + j;
    int col = g * 512 + u0 + j;
    int kbase = kq * 128;

    // phase-B mapping (tid<128)
    int ju = tid & 3, bb = tid >> 2;
    int ub = u0 + ju;
    float c_reg = 0.0f;
    float rm[4];
    if (tid < 128) {
#pragma unroll
        for (int g2 = 0; g2 < 4; g2++)
            rm[g2] = g_rmask[g2 * (BB*UU) + bb * UU + ub];
    }

    gridbar(NBLK);

    for (int t = 0; t < LL; t++) {
        int rbuf = (t + 1) & 1, wbuf = t & 1;

        // ---- phase A: partial z over this warp's k-quarter, 4 batches ----
        float a0, a1, a2, a3;
        if (kq == 0) {
            const float* zp = &g_zin[t * (BB*J4) + b0 * J4 + col];
            a0 = zp[0]; a1 = zp[J4]; a2 = zp[2*J4]; a3 = zp[3*J4];
        } else {
            a0 = a1 = a2 = a3 = 0.0f;
        }
        const float4* hp = ((const float4*)g_hmB)
                         + ((size_t)(rbuf * 4 + g) * 512 + kbase) * 8 + bq;
        const float* wrow = &sW[combo][kbase];
#pragma unroll 4
        for (int k = 0; k < 128; k += 4) {
            float4 w  = *(const float4*)&wrow[k];
            float4 h0 = __ldcg(hp + (k + 0) * 8);
            float4 h1 = __ldcg(hp + (k + 1) * 8);
            float4 h2 = __ldcg(hp + (k + 2) * 8);
            float4 h3 = __ldcg(hp + (k + 3) * 8);
            a0 += w.x*h0.x + w.y*h1.x + w.z*h2.x + w.w*h3.x;
            a1 += w.x*h0.y + w.y*h1.y + w.z*h2.y + w.w*h3.y;
            a2 += w.x*h0.z + w.y*h1.z + w.z*h2.z + w.w*h3.z;
            a3 += w.x*h0.w + w.y*h1.w + w.z*h2.w + w.w*h3.w;
        }
        *(float4*)&sZ[kq][combo][b0] = make_float4(a0, a1, a2, a3);
        __syncthreads();

        // ---- phase B: gates for (ub, bb) ----
        if (tid < 128) {
            float zi = sZ[0][ju      ][bb] + sZ[1][ju      ][bb]
                     + sZ[2][ju      ][bb] + sZ[3][ju      ][bb];
            float zf = sZ[0][4 + ju  ][bb] + sZ[1][4 + ju  ][bb]
                     + sZ[2][4 + ju  ][bb] + sZ[3][4 + ju  ][bb];
            float zg = sZ[0][8 + ju  ][bb] + sZ[1][8 + ju  ][bb]
                     + sZ[2][8 + ju  ][bb] + sZ[3][8 + ju  ][bb];
            float zo = sZ[0][12 + ju ][bb] + sZ[1][12 + ju ][bb]
                     + sZ[2][12 + ju ][bb] + sZ[3][12 + ju ][bb];
            float ig = 1.0f / (1.0f + expf(-zi));
            float fg = 1.0f / (1.0f + expf(-zf));
            float gg = tanhf(zg);
            float og = 1.0f / (1.0f + expf(-zo));
            c_reg = fg * c_reg + ig * gg;
            float h = og * tanhf(c_reg);
#pragma unroll
            for (int g2 = 0; g2 < 4; g2++)
                g_hmB[wbuf][g2][ub][bb] = h * rm[g2];
            int row = bb * LL + t;
            g_rnn[row * UU + ub] = h * g_fmask[row * UU + ub];
        }
        gridbar((unsigned)(t + 2) * NBLK);
    }
}

// ---------------- tf32 tensor-core GEMM, fragment-pipelined ----------------
__device__ inline uint32_t f2tf32(float x)
{
    uint32_t r;
    asm("cvt.rna.tf32.f32 %0, %1;" : "=r"(r) : "f"(x));
    return r;
}

__global__ __launch_bounds__(256) void tgemm_tf32(const float* __restrict__ A,
                                                  const float* __restrict__ Bm,
                                                  const float* __restrict__ bias,
                                                  float* __restrict__ C,
                                                  int M, int N, int K)
{
    __shared__ uint32_t As[2][128][20];
    __shared__ uint32_t Bs[2][16][132];

    int tid  = threadIdx.x;
    int lane = tid & 31, wid = tid >> 5;
    int wm0 = (wid >> 2) * 64;
    int wn0 = (wid & 3) * 32;
    int bm = blockIdx.y * 128, bn = blockIdx.x * 128;
    int t4 = lane >> 2, tq = lane & 3;

    int arow = tid >> 1, ac = (tid & 1) * 4;
    int brow = tid >> 4, bc = (tid & 15) * 8;

    const float* Abase = A + (size_t)(bm + arow) * K + ac;
    const float* Bbase = Bm + (size_t)brow * N + bn + bc;

    float4 av0, av1, bv0, bv1;

    float acc[4][4][4];
#pragma unroll
    for (int i = 0; i < 4; i++)
#pragma unroll
        for (int j = 0; j < 4; j++)
#pragma unroll
            for (int k = 0; k < 4; k++) acc[i][j][k] = 0.0f;

#define STORE_TILE(buf)                                                         \
    {                                                                           \
        uint4 ca0 = make_uint4(f2tf32(av0.x), f2tf32(av0.y),                    \
                               f2tf32(av0.z), f2tf32(av0.w));                   \
        uint4 ca1 = make_uint4(f2tf32(av1.x), f2tf32(av1.y),                    \
                               f2tf32(av1.z), f2tf32(av1.w));                   \
        *(uint4*)&As[buf][arow][ac]     = ca0;                                  \
        *(uint4*)&As[buf][arow][ac + 8] = ca1;                                  \
        uint4 cb0 = make_uint4(f2tf32(bv0.x), f2tf32(bv0.y),                    \
                               f2tf32(bv0.z), f2tf32(bv0.w));                   \
        uint4 cb1 = make_uint4(f2tf32(bv1.x), f2tf32(bv1.y),                    \
                               f2tf32(bv1.z), f2tf32(bv1.w));                   \
        *(uint4*)&Bs[buf][brow][bc]     = cb0;                                  \
        *(uint4*)&Bs[buf][brow][bc + 4] = cb1;                                  \
    }

#define LOADFRAG(af, bf, buf, kk)                                               \
    {                                                                           \
        _Pragma("unroll")                                                       \
        for (int mi = 0; mi < 4; mi++) {                                        \
            int r0 = wm0 + mi * 16 + t4;                                        \
            af[mi][0] = As[buf][r0    ][(kk) + tq];                             \
            af[mi][1] = As[buf][r0 + 8][(kk) + tq];                             \
            af[mi][2] = As[buf][r0    ][(kk) + 4 + tq];                         \
            af[mi][3] = As[buf][r0 + 8][(kk) + 4 + tq];                         \
        }                                                                       \
        _Pragma("unroll")                                                       \
        for (int nj = 0; nj < 4; nj++) {                                        \
            int ccol = wn0 + nj * 8 + t4;                                       \
            bf[nj][0] = Bs[buf][(kk) + tq][ccol];                               \
            bf[nj][1] = Bs[buf][(kk) + 4 + tq][ccol];                           \
        }                                                                       \
    }

#define MMA_SET(af, bf)                                                         \
    {                                                                           \
        _Pragma("unroll")                                                       \
        for (int mi = 0; mi < 4; mi++)                                          \
            _Pragma("unroll")                                                   \
            for (int nj = 0; nj < 4; nj++) {                                    \
                asm volatile(                                                   \
                    "mma.sync.aligned.m16n8k8.row.col.f32.tf32.tf32.f32 "       \
                    "{%0,%1,%2,%3}, {%4,%5,%6,%7}, {%8,%9}, {%0,%1,%2,%3};"     \
                    : "+f"(acc[mi][nj][0]), "+f"(acc[mi][nj][1]),               \
                      "+f"(acc[mi][nj][2]), "+f"(acc[mi][nj][3])                \
                    : "r"(af[mi][0]), "r"(af[mi][1]),                           \
                      "r"(af[mi][2]), "r"(af[mi][3]),                           \
                      "r"(bf[nj][0]), "r"(bf[nj][1]));                          \
            }                                                                   \
    }

    // prologue
    av0 = *(const float4*)(Abase);
    av1 = *(const float4*)(Abase + 8);
    bv0 = *(const float4*)(Bbase);
    bv1 = *(const float4*)(Bbase + 4);
    STORE_TILE(0);
    __syncthreads();

    uint32_t af0[4][4], bf0[4][2], af1[4][4], bf1[4][2];
    LOADFRAG(af0, bf0, 0, 0);

    int nt = K / 16;
    for (int kt = 0; kt < nt; kt++) {
        int cur = kt & 1;
        if (kt + 1 < nt) {
            const float* ap = Abase + (kt + 1) * 16;
            const float* bp = Bbase + (size_t)(kt + 1) * 16 * N;
            av0 = *(const float4*)(ap);
            av1 = *(const float4*)(ap + 8);
            bv0 = *(const float4*)(bp);
            bv1 = *(const float4*)(bp + 4);
        }
        LOADFRAG(af1, bf1, cur, 8);
        MMA_SET(af0, bf0);
        if (kt + 1 < nt) {
            int nxt = (kt + 1) & 1;
            __syncthreads();
            STORE_TILE(nxt);
            __syncthreads();
            LOADFRAG(af0, bf0, nxt, 0);
        }
        MMA_SET(af1, bf1);
    }
#undef STORE_TILE
#undef LOADFRAG
#undef MMA_SET

    // epilogue
#pragma unroll
    for (int mi = 0; mi < 4; mi++) {
        int r0 = bm + wm0 + mi * 16 + t4;
#pragma unroll
        for (int nj = 0; nj < 4; nj++) {
            int col = bn + wn0 + nj * 8 + tq * 2;
            float b0 = bias[col], b1 = bias[col + 1];
            float2 v0 = make_float2(acc[mi][nj][0] + b0, acc[mi][nj][1] + b1);
            float2 v1 = make_float2(acc[mi][nj][2] + b0, acc[mi][nj][3] + b1);
            *(float2*)&C[(size_t)r0 * N + col]       = v0;
            *(float2*)&C[(size_t)(r0 + 8) * N + col] = v1;
        }
    }
}

// ---------------- launch ----------------
extern "C" void kernel_launch(void* const* d_in, const int* in_sizes, int n_in,
                              void* d_out, int out_size)
{
    const float* images = (const float*)d_in[1];
    const void*  targs  =                d_in[2];
    const float* emb    = (const float*)d_in[3];
    const float* W_in   = (const float*)d_in[4];
    const float* W_rec  = (const float*)d_in[5];
    const float* b_lstm = (const float*)d_in[6];
    const float* W_out  = (const float*)d_in[7];
    const float* b_out  = (const float*)d_in[8];
    float* out = (float*)d_out;

    uint32_t k1a,k1b, k2a,k2b, k3a,k3b;
    tf2x32(0u, 42u, 0u, 0u, &k1a, &k1b);
    tf2x32(0u, 42u, 0u, 1u, &k2a, &k2b);
    tf2x32(0u, 42u, 0u, 2u, &k3a, &k3b);

    float *p_x, *p_zin, *p_rnn;
    cudaGetSymbolAddress((void**)&p_x,   g_x);
    cudaGetSymbolAddress((void**)&p_zin, g_zin);
    cudaGetSymbolAddress((void**)&p_rnn, g_rnn);

    prep_kernel<<<PREP_BLOCKS, 256>>>(k1a, k1b, k2a, k2b, k3a, k3b,
                                      (const unsigned int*)targs);
    embed_kernel<<<(LL*BB*EE) / 256, 256>>>(images, targs, emb);
    sgemm128<<<dim3(J4/128, (LL*BB)/128), 256>>>(p_x, W_in, b_lstm, p_zin, LL*BB, J4, EE);
    lstm_persist<<<NBLK, 512>>>(W_rec);
    tgemm_tf32<<<dim3(VV/128, (BB*LL)/128), 256>>>(p_rnn, W_out, b_out, out, BB*LL, VV, UU);
}